// round 5
// baseline (speedup 1.0000x reference)
#include <cuda_runtime.h>
#include <cstdint>

#define N_NODES 50000
#define F_IN    512
#define NH1     8
#define C1      8
#define D1      64   // NH1*C1
#define C2      40

// ---------------- scratch (device globals; no allocation) ----------------
__device__ __align__(256) float g_h1  [N_NODES * D1];
__device__ __align__(256) float g_as1 [N_NODES * NH1];
__device__ __align__(256) float g_ad1 [N_NODES * NH1];
__device__ __align__(256) float g_den1[N_NODES * NH1];
__device__ __align__(256) float g_acc1[N_NODES * D1];   // reused as relu output
__device__ __align__(256) float g_h2  [N_NODES * C2];
__device__ __align__(256) float g_as2 [N_NODES];
__device__ __align__(256) float g_ad2 [N_NODES];
__device__ __align__(256) float g_den2[N_NODES];
__device__ __align__(256) float g_acc2[N_NODES * C2];
__device__ int g_is64;   // 1 if edge_index buffer is int64, 0 if int32

__device__ __forceinline__ float leaky(float e) { return e >= 0.f ? e : 0.2f * e; }

__device__ __forceinline__ void red_add4(float* p, float a, float b, float c, float d) {
    asm volatile("red.global.add.v4.f32 [%0], {%1,%2,%3,%4};"
                 :: "l"(p), "f"(a), "f"(b), "f"(c), "f"(d) : "memory");
}

// Load edge endpoints robustly w.r.t. index dtype (int32 vs int64).
__device__ __forceinline__ void load_edge(const void* ei, int E, int e, int& s, int& d) {
    if (g_is64) {
        const long long* p = (const long long*)ei;
        s = (int)p[e];
        d = (int)p[E + e];
    } else {
        const int* p = (const int*)ei;
        s = p[e];
        d = p[E + e];
    }
}

// ---------------- dtype detect (1 thread) ----------------
__global__ void detect_kernel(const unsigned int* __restrict__ ei_raw) {
    if (threadIdx.x == 0 && blockIdx.x == 0) {
        int all_zero = 1;
        for (int i = 0; i < 32; i++)
            if (ei_raw[2 * i + 1] != 0u) { all_zero = 0; break; }
        g_is64 = all_zero;   // int64 little-endian with values<2^31 -> odd words all zero
    }
}

// ---------------- zero the accumulators ----------------
__global__ void zero_kernel() {
    int i = blockIdx.x * blockDim.x + threadIdx.x;
    int stride = gridDim.x * blockDim.x;
    float4 z = make_float4(0.f, 0.f, 0.f, 0.f);
    for (int j = i; j < N_NODES * D1 / 4;  j += stride) ((float4*)g_acc1)[j] = z;
    for (int j = i; j < N_NODES * NH1 / 4; j += stride) ((float4*)g_den1)[j] = z;
    for (int j = i; j < N_NODES * C2 / 4;  j += stride) ((float4*)g_acc2)[j] = z;
    for (int j = i; j < N_NODES / 4;       j += stride) ((float4*)g_den2)[j] = z;
}

// ---------------- GEMM1: h1[N,64] = x[N,512] @ W1[512,64] ----------------
#define BM 128
#define BK 16
__global__ __launch_bounds__(256) void gemm1_kernel(const float* __restrict__ x,
                                                    const float* __restrict__ W) {
    __shared__ float As[BK][BM + 4];
    __shared__ float Bs[BK][D1];
    int tid = threadIdx.x;
    int m0 = blockIdx.x * BM;
    int trow = tid >> 4;   // 0..15 -> rows trow*8..trow*8+7
    int tcol = tid & 15;   // cols tcol*4..tcol*4+3
    float acc[8][4];
#pragma unroll
    for (int i = 0; i < 8; i++)
#pragma unroll
        for (int j = 0; j < 4; j++) acc[i][j] = 0.f;

    for (int k0 = 0; k0 < F_IN; k0 += BK) {
        // load A tile (128 rows x 16 k), transpose into As[k][m]
#pragma unroll
        for (int l = 0; l < 2; l++) {
            int flat = tid * 2 + l;       // 0..511
            int m  = flat >> 2;           // 0..127
            int kv = (flat & 3) * 4;      // 0,4,8,12
            float4 v = make_float4(0.f, 0.f, 0.f, 0.f);
            int gr = m0 + m;
            if (gr < N_NODES)
                v = *(const float4*)(x + (size_t)gr * F_IN + k0 + kv);
            As[kv + 0][m] = v.x; As[kv + 1][m] = v.y;
            As[kv + 2][m] = v.z; As[kv + 3][m] = v.w;
        }
        // load B tile (16 k x 64 cols)
        {
            int kb = tid >> 4;
            int cb = (tid & 15) * 4;
            float4 v = *(const float4*)(W + (size_t)(k0 + kb) * D1 + cb);
            *(float4*)&Bs[kb][cb] = v;
        }
        __syncthreads();
#pragma unroll
        for (int k = 0; k < BK; k++) {
            float a[8], b[4];
            *(float4*)&a[0] = *(float4*)&As[k][trow * 8];
            *(float4*)&a[4] = *(float4*)&As[k][trow * 8 + 4];
            *(float4*)&b[0] = *(float4*)&Bs[k][tcol * 4];
#pragma unroll
            for (int i = 0; i < 8; i++)
#pragma unroll
                for (int j = 0; j < 4; j++) acc[i][j] += a[i] * b[j];
        }
        __syncthreads();
    }
#pragma unroll
    for (int i = 0; i < 8; i++) {
        int gr = m0 + trow * 8 + i;
        if (gr < N_NODES) {
            float4 v = make_float4(acc[i][0], acc[i][1], acc[i][2], acc[i][3]);
            *(float4*)(g_h1 + (size_t)gr * D1 + tcol * 4) = v;
        }
    }
}

// ---------------- per-node attention logits, layer 1 ----------------
__global__ void att1_kernel(const float* __restrict__ att_src,
                            const float* __restrict__ att_dst) {
    int n = blockIdx.x * blockDim.x + threadIdx.x;
    if (n >= N_NODES) return;
    const float4* hr = (const float4*)(g_h1 + (size_t)n * D1);
    float as[NH1], ad[NH1];
#pragma unroll
    for (int h = 0; h < NH1; h++) { as[h] = 0.f; ad[h] = 0.f; }
#pragma unroll
    for (int j = 0; j < 16; j++) {
        float4 v = __ldg(hr + j);
        float4 s = __ldg((const float4*)att_src + j);
        float4 d = __ldg((const float4*)att_dst + j);
        int h = j >> 1;
        as[h] += v.x * s.x + v.y * s.y + v.z * s.z + v.w * s.w;
        ad[h] += v.x * d.x + v.y * d.y + v.z * d.z + v.w * d.w;
    }
    *(float4*)(g_as1 + (size_t)n * NH1)     = make_float4(as[0], as[1], as[2], as[3]);
    *(float4*)(g_as1 + (size_t)n * NH1 + 4) = make_float4(as[4], as[5], as[6], as[7]);
    *(float4*)(g_ad1 + (size_t)n * NH1)     = make_float4(ad[0], ad[1], ad[2], ad[3]);
    *(float4*)(g_ad1 + (size_t)n * NH1 + 4) = make_float4(ad[4], ad[5], ad[6], ad[7]);
}

// ---------------- layer-1 edge pass (unnormalized softmax scatter) ----------------
__global__ __launch_bounds__(256) void edge1_kernel(const void* __restrict__ ei, int E) {
    int e = blockIdx.x * blockDim.x + threadIdx.x;
    if (e >= E) return;
    int s, d;
    load_edge(ei, E, e, s, d);
    if ((unsigned)s >= N_NODES || (unsigned)d >= N_NODES) return;  // safety net
    const float4* asp = (const float4*)(g_as1 + (size_t)s * NH1);
    const float4* adp = (const float4*)(g_ad1 + (size_t)d * NH1);
    float4 a0 = __ldg(asp), a1 = __ldg(asp + 1);
    float4 b0 = __ldg(adp), b1 = __ldg(adp + 1);
    float w[8];
    w[0] = __expf(leaky(a0.x + b0.x));
    w[1] = __expf(leaky(a0.y + b0.y));
    w[2] = __expf(leaky(a0.z + b0.z));
    w[3] = __expf(leaky(a0.w + b0.w));
    w[4] = __expf(leaky(a1.x + b1.x));
    w[5] = __expf(leaky(a1.y + b1.y));
    w[6] = __expf(leaky(a1.z + b1.z));
    w[7] = __expf(leaky(a1.w + b1.w));
    float* den = g_den1 + (size_t)d * NH1;
    red_add4(den,     w[0], w[1], w[2], w[3]);
    red_add4(den + 4, w[4], w[5], w[6], w[7]);
    const float4* hs = (const float4*)(g_h1 + (size_t)s * D1);
    float* ap = g_acc1 + (size_t)d * D1;
#pragma unroll
    for (int j = 0; j < 16; j++) {
        float4 v = __ldg(hs + j);
        float sc = w[j >> 1];
        red_add4(ap + j * 4, v.x * sc, v.y * sc, v.z * sc, v.w * sc);
    }
}

// ---------------- layer-1 finalize: self-loop + normalize + bias + relu ----------------
__global__ void fin1_kernel(const float* __restrict__ b1) {
    int i = blockIdx.x * blockDim.x + threadIdx.x;
    if (i >= N_NODES * D1) return;
    int n = i >> 6;
    int c = i & 63;
    int h = c >> 3;
    float ws = __expf(leaky(g_as1[n * NH1 + h] + g_ad1[n * NH1 + h]));
    float v = (g_acc1[i] + ws * g_h1[i]) / (g_den1[n * NH1 + h] + ws + 1e-16f) + __ldg(b1 + c);
    g_acc1[i] = fmaxf(v, 0.f);   // in-place: becomes layer-2 input
}

// ---------------- GEMM2: h2[N,40] = relu[N,64] @ W2[64,40] ----------------
__global__ __launch_bounds__(256) void gemm2_kernel(const float* __restrict__ W2) {
    __shared__ float xs[32 * D1];
    __shared__ float ws[D1 * C2];
    int tid = threadIdx.x;
    int n0 = blockIdx.x * 32;
    for (int j = tid; j < D1 * C2 / 4; j += 256)
        ((float4*)ws)[j] = __ldg((const float4*)W2 + j);
    for (int j = tid; j < 32 * D1 / 4; j += 256) {
        int nn = j >> 4;
        float4 v = make_float4(0.f, 0.f, 0.f, 0.f);
        if (n0 + nn < N_NODES)
            v = *((const float4*)(g_acc1 + (size_t)(n0 + nn) * D1) + (j & 15));
        ((float4*)xs)[j] = v;
    }
    __syncthreads();
#pragma unroll
    for (int t = 0; t < 5; t++) {
        int flat = t * 256 + tid;        // 0..1279
        int i = flat / C2;
        int c = flat % C2;
        float sum = 0.f;
#pragma unroll
        for (int kk = 0; kk < D1; kk++) sum += xs[i * D1 + kk] * ws[kk * C2 + c];
        int n = n0 + i;
        if (n < N_NODES) g_h2[(size_t)n * C2 + c] = sum;
    }
}

// ---------------- per-node attention logits, layer 2 ----------------
__global__ void att2_kernel(const float* __restrict__ att_src,
                            const float* __restrict__ att_dst) {
    int n = blockIdx.x * blockDim.x + threadIdx.x;
    if (n >= N_NODES) return;
    const float4* hr = (const float4*)(g_h2 + (size_t)n * C2);
    float as = 0.f, ad = 0.f;
#pragma unroll
    for (int j = 0; j < 10; j++) {
        float4 v = __ldg(hr + j);
        float4 s = __ldg((const float4*)att_src + j);
        float4 d = __ldg((const float4*)att_dst + j);
        as += v.x * s.x + v.y * s.y + v.z * s.z + v.w * s.w;
        ad += v.x * d.x + v.y * d.y + v.z * d.z + v.w * d.w;
    }
    g_as2[n] = as;
    g_ad2[n] = ad;
}

// ---------------- layer-2 edge pass ----------------
__global__ __launch_bounds__(256) void edge2_kernel(const void* __restrict__ ei, int E) {
    int e = blockIdx.x * blockDim.x + threadIdx.x;
    if (e >= E) return;
    int s, d;
    load_edge(ei, E, e, s, d);
    if ((unsigned)s >= N_NODES || (unsigned)d >= N_NODES) return;  // safety net
    float w = __expf(leaky(__ldg(g_as2 + s) + __ldg(g_ad2 + d)));
    atomicAdd(g_den2 + d, w);
    const float4* hs = (const float4*)(g_h2 + (size_t)s * C2);
    float* ap = g_acc2 + (size_t)d * C2;
#pragma unroll
    for (int j = 0; j < 10; j++) {
        float4 v = __ldg(hs + j);
        red_add4(ap + j * 4, v.x * w, v.y * w, v.z * w, v.w * w);
    }
}

// ---------------- layer-2 finalize + log_softmax (warp per node) ----------------
__global__ void fin2_kernel(const float* __restrict__ b2, float* __restrict__ out) {
    int gtid = blockIdx.x * blockDim.x + threadIdx.x;
    int n = gtid >> 5;
    int lane = threadIdx.x & 31;
    if (n >= N_NODES) return;
    float ws = __expf(leaky(g_as2[n] + g_ad2[n]));
    float inv = 1.f / (g_den2[n] + ws + 1e-16f);
    int c0 = lane, c1 = lane + 32;
    float v0, v1 = -1e30f;
    v0 = (g_acc2[(size_t)n * C2 + c0] + ws * g_h2[(size_t)n * C2 + c0]) * inv + __ldg(b2 + c0);
    if (c1 < C2)
        v1 = (g_acc2[(size_t)n * C2 + c1] + ws * g_h2[(size_t)n * C2 + c1]) * inv + __ldg(b2 + c1);
    float m = fmaxf(v0, v1);
#pragma unroll
    for (int o = 16; o; o >>= 1) m = fmaxf(m, __shfl_xor_sync(0xffffffffu, m, o));
    float sEx = __expf(v0 - m) + ((c1 < C2) ? __expf(v1 - m) : 0.f);
#pragma unroll
    for (int o = 16; o; o >>= 1) sEx += __shfl_xor_sync(0xffffffffu, sEx, o);
    float lse = m + __logf(sEx);
    out[(size_t)n * C2 + c0] = v0 - lse;
    if (c1 < C2) out[(size_t)n * C2 + c1] = v1 - lse;
}

// ---------------- launch ----------------
extern "C" void kernel_launch(void* const* d_in, const int* in_sizes, int n_in,
                              void* d_out, int out_size) {
    const float* x    = (const float*)d_in[0];
    const void*  ei   = d_in[1];
    const float* W1   = (const float*)d_in[2];
    const float* asr1 = (const float*)d_in[3];
    const float* adt1 = (const float*)d_in[4];
    const float* b1   = (const float*)d_in[5];
    const float* W2   = (const float*)d_in[6];
    const float* asr2 = (const float*)d_in[7];
    const float* adt2 = (const float*)d_in[8];
    const float* b2   = (const float*)d_in[9];
    int E = in_sizes[1] / 2;
    float* out = (float*)d_out;

    detect_kernel<<<1, 32>>>((const unsigned int*)ei);
    zero_kernel<<<1024, 256>>>();
    gemm1_kernel<<<(N_NODES + BM - 1) / BM, 256>>>(x, W1);
    att1_kernel<<<(N_NODES + 255) / 256, 256>>>(asr1, adt1);
    edge1_kernel<<<(E + 255) / 256, 256>>>(ei, E);
    fin1_kernel<<<(N_NODES * D1 + 255) / 256, 256>>>(b1);
    gemm2_kernel<<<(N_NODES + 31) / 32, 256>>>(W2);
    att2_kernel<<<(N_NODES + 255) / 256, 256>>>(asr2, adt2);
    edge2_kernel<<<(E + 255) / 256, 256>>>(ei, E);
    fin2_kernel<<<(N_NODES + 7) / 8, 256>>>(b2, out);
}

// round 6
// speedup vs baseline: 1.0955x; 1.0955x over previous
#include <cuda_runtime.h>
#include <cstdint>

#define N_NODES 50000
#define F_IN    512
#define NH1     8
#define C1      8
#define D1      64   // NH1*C1
#define C2      40
#define ECAP    1600000

// ---------------- scratch (device globals; no allocation) ----------------
__device__ __align__(256) float g_h1  [N_NODES * D1];
__device__ __align__(256) float g_as1 [N_NODES * NH1];
__device__ __align__(256) float g_ad1 [N_NODES * NH1];
__device__ __align__(256) float g_den1[N_NODES * NH1];
__device__ __align__(256) float g_acc1[N_NODES * D1];   // reused as relu output
__device__ __align__(256) float g_h2  [N_NODES * C2];
__device__ __align__(256) float g_as2 [N_NODES];
__device__ __align__(256) float g_ad2 [N_NODES];
__device__ __align__(256) float g_den2[N_NODES];
__device__ __align__(256) float g_acc2[N_NODES * C2];
__device__ __align__(256) int   g_src [ECAP];
__device__ __align__(256) int   g_dst [ECAP];
__device__ int g_is64;   // 1 if edge_index buffer is int64, 0 if int32

__device__ __forceinline__ float leaky(float e) { return e >= 0.f ? e : 0.2f * e; }

__device__ __forceinline__ void red_add4(float* p, float a, float b, float c, float d) {
    asm volatile("red.global.add.v4.f32 [%0], {%1,%2,%3,%4};"
                 :: "l"(p), "f"(a), "f"(b), "f"(c), "f"(d) : "memory");
}

__device__ __forceinline__ uint32_t f2tf32(float f) {
    uint32_t r;
    asm("cvt.rna.tf32.f32 %0, %1;" : "=r"(r) : "f"(f));
    return r;
}

__device__ __forceinline__ void mma_tf32(float* c, const uint32_t* a, const uint32_t* b) {
    asm volatile("mma.sync.aligned.m16n8k8.row.col.f32.tf32.tf32.f32 "
                 "{%0,%1,%2,%3}, {%4,%5,%6,%7}, {%8,%9}, {%0,%1,%2,%3};"
                 : "+f"(c[0]), "+f"(c[1]), "+f"(c[2]), "+f"(c[3])
                 : "r"(a[0]), "r"(a[1]), "r"(a[2]), "r"(a[3]),
                   "r"(b[0]), "r"(b[1]));
}

// ---------------- dtype detect (1 thread) ----------------
__global__ void detect_kernel(const unsigned int* __restrict__ ei_raw) {
    if (threadIdx.x == 0 && blockIdx.x == 0) {
        int all_zero = 1;
        for (int i = 0; i < 32; i++)
            if (ei_raw[2 * i + 1] != 0u) { all_zero = 0; break; }
        g_is64 = all_zero;   // int64 little-endian with values<2^31 -> odd words all zero
    }
}

// ---------------- convert edge index to packed int32 ----------------
__global__ void convert_kernel(const void* __restrict__ ei, int E) {
    int e = blockIdx.x * blockDim.x + threadIdx.x;
    if (e >= E || e >= ECAP) return;
    int s, d;
    if (g_is64) {
        const long long* p = (const long long*)ei;
        s = (int)p[e];
        d = (int)p[E + e];
    } else {
        const int* p = (const int*)ei;
        s = p[e];
        d = p[E + e];
    }
    g_src[e] = s;
    g_dst[e] = d;
}

// ---------------- zero the accumulators ----------------
__global__ void zero_kernel() {
    int i = blockIdx.x * blockDim.x + threadIdx.x;
    int stride = gridDim.x * blockDim.x;
    float4 z = make_float4(0.f, 0.f, 0.f, 0.f);
    for (int j = i; j < N_NODES * D1 / 4;  j += stride) ((float4*)g_acc1)[j] = z;
    for (int j = i; j < N_NODES * NH1 / 4; j += stride) ((float4*)g_den1)[j] = z;
    for (int j = i; j < N_NODES * C2 / 4;  j += stride) ((float4*)g_acc2)[j] = z;
    for (int j = i; j < N_NODES / 4;       j += stride) ((float4*)g_den2)[j] = z;
}

// ---------------- GEMM1 (tensor core tf32): h1[N,64] = x[N,512] @ W1[512,64] ----------------
// Block: 128 rows x 64 cols, 8 warps as 4(m) x 2(n); warp tile 32x32 = 2x4 mma tiles.
#define GA_STR 36
#define GB_STR 72
__global__ __launch_bounds__(256) void gemm1_tc(const float* __restrict__ x,
                                                const float* __restrict__ W) {
    __shared__ uint32_t As[128 * GA_STR];  // [m][k], tf32 bits
    __shared__ uint32_t Bs[32 * GB_STR];   // [k][n], tf32 bits
    int tid  = threadIdx.x;
    int m0   = blockIdx.x * 128;
    int wid  = tid >> 5, lane = tid & 31;
    int wm   = wid >> 1, wn = wid & 1;
    int g    = lane >> 2, tig = lane & 3;

    float acc[2][4][4];
#pragma unroll
    for (int mt = 0; mt < 2; mt++)
#pragma unroll
        for (int nt = 0; nt < 4; nt++)
#pragma unroll
            for (int j = 0; j < 4; j++) acc[mt][nt][j] = 0.f;

    for (int k0 = 0; k0 < F_IN; k0 += 32) {
        // A tile: 128 x 32, coalesced float4 loads, convert to tf32
#pragma unroll
        for (int l = 0; l < 4; l++) {
            int idx = l * 256 + tid;        // 0..1023
            int m  = idx >> 3;              // 0..127
            int kv = (idx & 7) * 4;         // 0..28
            float4 v = make_float4(0.f, 0.f, 0.f, 0.f);
            if (m0 + m < N_NODES)
                v = *(const float4*)(x + (size_t)(m0 + m) * F_IN + k0 + kv);
            As[m * GA_STR + kv + 0] = f2tf32(v.x);
            As[m * GA_STR + kv + 1] = f2tf32(v.y);
            As[m * GA_STR + kv + 2] = f2tf32(v.z);
            As[m * GA_STR + kv + 3] = f2tf32(v.w);
        }
        // B tile: 32 x 64
#pragma unroll
        for (int l = 0; l < 2; l++) {
            int idx = l * 256 + tid;        // 0..511
            int r  = idx >> 4;              // 0..31
            int cv = (idx & 15) * 4;        // 0..60
            float4 v = *(const float4*)(W + (size_t)(k0 + r) * D1 + cv);
            Bs[r * GB_STR + cv + 0] = f2tf32(v.x);
            Bs[r * GB_STR + cv + 1] = f2tf32(v.y);
            Bs[r * GB_STR + cv + 2] = f2tf32(v.z);
            Bs[r * GB_STR + cv + 3] = f2tf32(v.w);
        }
        __syncthreads();
#pragma unroll
        for (int kk = 0; kk < 4; kk++) {
            int kb = kk * 8;
            uint32_t a[2][4], b[4][2];
#pragma unroll
            for (int mt = 0; mt < 2; mt++) {
                int r = wm * 32 + mt * 16;
                a[mt][0] = As[(r + g    ) * GA_STR + kb + tig    ];
                a[mt][1] = As[(r + g + 8) * GA_STR + kb + tig    ];
                a[mt][2] = As[(r + g    ) * GA_STR + kb + tig + 4];
                a[mt][3] = As[(r + g + 8) * GA_STR + kb + tig + 4];
            }
#pragma unroll
            for (int nt = 0; nt < 4; nt++) {
                int c = wn * 32 + nt * 8 + g;
                b[nt][0] = Bs[(kb + tig    ) * GB_STR + c];
                b[nt][1] = Bs[(kb + tig + 4) * GB_STR + c];
            }
#pragma unroll
            for (int mt = 0; mt < 2; mt++)
#pragma unroll
                for (int nt = 0; nt < 4; nt++)
                    mma_tf32(acc[mt][nt], a[mt], b[nt]);
        }
        __syncthreads();
    }
    // epilogue: c0=(g,2t) c1=(g,2t+1) c2=(g+8,2t) c3=(g+8,2t+1)
#pragma unroll
    for (int mt = 0; mt < 2; mt++)
#pragma unroll
        for (int nt = 0; nt < 4; nt++) {
            int r = m0 + wm * 32 + mt * 16 + g;
            int c = wn * 32 + nt * 8 + tig * 2;
            if (r < N_NODES)
                *(float2*)(g_h1 + (size_t)r * D1 + c) =
                    make_float2(acc[mt][nt][0], acc[mt][nt][1]);
            if (r + 8 < N_NODES)
                *(float2*)(g_h1 + (size_t)(r + 8) * D1 + c) =
                    make_float2(acc[mt][nt][2], acc[mt][nt][3]);
        }
}

// ---------------- per-node attention logits, layer 1 ----------------
__global__ void att1_kernel(const float* __restrict__ att_src,
                            const float* __restrict__ att_dst) {
    int n = blockIdx.x * blockDim.x + threadIdx.x;
    if (n >= N_NODES) return;
    const float4* hr = (const float4*)(g_h1 + (size_t)n * D1);
    float as[NH1], ad[NH1];
#pragma unroll
    for (int h = 0; h < NH1; h++) { as[h] = 0.f; ad[h] = 0.f; }
#pragma unroll
    for (int j = 0; j < 16; j++) {
        float4 v = __ldg(hr + j);
        float4 s = __ldg((const float4*)att_src + j);
        float4 d = __ldg((const float4*)att_dst + j);
        int h = j >> 1;
        as[h] += v.x * s.x + v.y * s.y + v.z * s.z + v.w * s.w;
        ad[h] += v.x * d.x + v.y * d.y + v.z * d.z + v.w * d.w;
    }
    *(float4*)(g_as1 + (size_t)n * NH1)     = make_float4(as[0], as[1], as[2], as[3]);
    *(float4*)(g_as1 + (size_t)n * NH1 + 4) = make_float4(as[4], as[5], as[6], as[7]);
    *(float4*)(g_ad1 + (size_t)n * NH1)     = make_float4(ad[0], ad[1], ad[2], ad[3]);
    *(float4*)(g_ad1 + (size_t)n * NH1 + 4) = make_float4(ad[4], ad[5], ad[6], ad[7]);
}

// ---------------- layer-1 edge pass (unnormalized softmax scatter) ----------------
__global__ __launch_bounds__(256) void edge1_kernel(int E) {
    int e = blockIdx.x * blockDim.x + threadIdx.x;
    if (e >= E) return;
    int s = g_src[e];
    int d = g_dst[e];
    if ((unsigned)s >= N_NODES || (unsigned)d >= N_NODES) return;  // safety net
    const float4* asp = (const float4*)(g_as1 + (size_t)s * NH1);
    const float4* adp = (const float4*)(g_ad1 + (size_t)d * NH1);
    float4 a0 = __ldg(asp), a1 = __ldg(asp + 1);
    float4 b0 = __ldg(adp), b1 = __ldg(adp + 1);
    float w[8];
    w[0] = __expf(leaky(a0.x + b0.x));
    w[1] = __expf(leaky(a0.y + b0.y));
    w[2] = __expf(leaky(a0.z + b0.z));
    w[3] = __expf(leaky(a0.w + b0.w));
    w[4] = __expf(leaky(a1.x + b1.x));
    w[5] = __expf(leaky(a1.y + b1.y));
    w[6] = __expf(leaky(a1.z + b1.z));
    w[7] = __expf(leaky(a1.w + b1.w));
    float* den = g_den1 + (size_t)d * NH1;
    red_add4(den,     w[0], w[1], w[2], w[3]);
    red_add4(den + 4, w[4], w[5], w[6], w[7]);
    const float4* hs = (const float4*)(g_h1 + (size_t)s * D1);
    float* ap = g_acc1 + (size_t)d * D1;
#pragma unroll
    for (int j = 0; j < 16; j++) {
        float4 v = __ldg(hs + j);
        float sc = w[j >> 1];
        red_add4(ap + j * 4, v.x * sc, v.y * sc, v.z * sc, v.w * sc);
    }
}

// ---------------- layer-1 finalize: self-loop + normalize + bias + relu ----------------
__global__ void fin1_kernel(const float* __restrict__ b1) {
    int i = blockIdx.x * blockDim.x + threadIdx.x;
    if (i >= N_NODES * D1) return;
    int n = i >> 6;
    int c = i & 63;
    int h = c >> 3;
    float ws = __expf(leaky(g_as1[n * NH1 + h] + g_ad1[n * NH1 + h]));
    float v = (g_acc1[i] + ws * g_h1[i]) / (g_den1[n * NH1 + h] + ws + 1e-16f) + __ldg(b1 + c);
    g_acc1[i] = fmaxf(v, 0.f);   // in-place: becomes layer-2 input
}

// ---------------- GEMM2: h2[N,40] = relu[N,64] @ W2[64,40] ----------------
__global__ __launch_bounds__(256) void gemm2_kernel(const float* __restrict__ W2) {
    __shared__ float xs[32 * D1];
    __shared__ float ws[D1 * C2];
    int tid = threadIdx.x;
    int n0 = blockIdx.x * 32;
    for (int j = tid; j < D1 * C2 / 4; j += 256)
        ((float4*)ws)[j] = __ldg((const float4*)W2 + j);
    for (int j = tid; j < 32 * D1 / 4; j += 256) {
        int nn = j >> 4;
        float4 v = make_float4(0.f, 0.f, 0.f, 0.f);
        if (n0 + nn < N_NODES)
            v = *((const float4*)(g_acc1 + (size_t)(n0 + nn) * D1) + (j & 15));
        ((float4*)xs)[j] = v;
    }
    __syncthreads();
#pragma unroll
    for (int t = 0; t < 5; t++) {
        int flat = t * 256 + tid;        // 0..1279
        int i = flat / C2;
        int c = flat % C2;
        float sum = 0.f;
#pragma unroll
        for (int kk = 0; kk < D1; kk++) sum += xs[i * D1 + kk] * ws[kk * C2 + c];
        int n = n0 + i;
        if (n < N_NODES) g_h2[(size_t)n * C2 + c] = sum;
    }
}

// ---------------- per-node attention logits, layer 2 ----------------
__global__ void att2_kernel(const float* __restrict__ att_src,
                            const float* __restrict__ att_dst) {
    int n = blockIdx.x * blockDim.x + threadIdx.x;
    if (n >= N_NODES) return;
    const float4* hr = (const float4*)(g_h2 + (size_t)n * C2);
    float as = 0.f, ad = 0.f;
#pragma unroll
    for (int j = 0; j < 10; j++) {
        float4 v = __ldg(hr + j);
        float4 s = __ldg((const float4*)att_src + j);
        float4 d = __ldg((const float4*)att_dst + j);
        as += v.x * s.x + v.y * s.y + v.z * s.z + v.w * s.w;
        ad += v.x * d.x + v.y * d.y + v.z * d.z + v.w * d.w;
    }
    g_as2[n] = as;
    g_ad2[n] = ad;
}

// ---------------- layer-2 edge pass ----------------
__global__ __launch_bounds__(256) void edge2_kernel(int E) {
    int e = blockIdx.x * blockDim.x + threadIdx.x;
    if (e >= E) return;
    int s = g_src[e];
    int d = g_dst[e];
    if ((unsigned)s >= N_NODES || (unsigned)d >= N_NODES) return;  // safety net
    float w = __expf(leaky(__ldg(g_as2 + s) + __ldg(g_ad2 + d)));
    atomicAdd(g_den2 + d, w);
    const float4* hs = (const float4*)(g_h2 + (size_t)s * C2);
    float* ap = g_acc2 + (size_t)d * C2;
#pragma unroll
    for (int j = 0; j < 10; j++) {
        float4 v = __ldg(hs + j);
        red_add4(ap + j * 4, v.x * w, v.y * w, v.z * w, v.w * w);
    }
}

// ---------------- layer-2 finalize + log_softmax (warp per node) ----------------
__global__ void fin2_kernel(const float* __restrict__ b2, float* __restrict__ out) {
    int gtid = blockIdx.x * blockDim.x + threadIdx.x;
    int n = gtid >> 5;
    int lane = threadIdx.x & 31;
    if (n >= N_NODES) return;
    float ws = __expf(leaky(g_as2[n] + g_ad2[n]));
    float inv = 1.f / (g_den2[n] + ws + 1e-16f);
    int c0 = lane, c1 = lane + 32;
    float v0, v1 = -1e30f;
    v0 = (g_acc2[(size_t)n * C2 + c0] + ws * g_h2[(size_t)n * C2 + c0]) * inv + __ldg(b2 + c0);
    if (c1 < C2)
        v1 = (g_acc2[(size_t)n * C2 + c1] + ws * g_h2[(size_t)n * C2 + c1]) * inv + __ldg(b2 + c1);
    float m = fmaxf(v0, v1);
#pragma unroll
    for (int o = 16; o; o >>= 1) m = fmaxf(m, __shfl_xor_sync(0xffffffffu, m, o));
    float sEx = __expf(v0 - m) + ((c1 < C2) ? __expf(v1 - m) : 0.f);
#pragma unroll
    for (int o = 16; o; o >>= 1) sEx += __shfl_xor_sync(0xffffffffu, sEx, o);
    float lse = m + __logf(sEx);
    out[(size_t)n * C2 + c0] = v0 - lse;
    if (c1 < C2) out[(size_t)n * C2 + c1] = v1 - lse;
}

// ---------------- launch ----------------
extern "C" void kernel_launch(void* const* d_in, const int* in_sizes, int n_in,
                              void* d_out, int out_size) {
    const float* x    = (const float*)d_in[0];
    const void*  ei   = d_in[1];
    const float* W1   = (const float*)d_in[2];
    const float* asr1 = (const float*)d_in[3];
    const float* adt1 = (const float*)d_in[4];
    const float* b1   = (const float*)d_in[5];
    const float* W2   = (const float*)d_in[6];
    const float* asr2 = (const float*)d_in[7];
    const float* adt2 = (const float*)d_in[8];
    const float* b2   = (const float*)d_in[9];
    int E = in_sizes[1] / 2;
    float* out = (float*)d_out;

    detect_kernel<<<1, 32>>>((const unsigned int*)ei);
    convert_kernel<<<(E + 255) / 256, 256>>>(ei, E);
    zero_kernel<<<1024, 256>>>();
    gemm1_tc<<<(N_NODES + 127) / 128, 256>>>(x, W1);
    att1_kernel<<<(N_NODES + 255) / 256, 256>>>(asr1, adt1);
    edge1_kernel<<<(E + 255) / 256, 256>>>(E);
    fin1_kernel<<<(N_NODES * D1 + 255) / 256, 256>>>(b1);
    gemm2_kernel<<<(N_NODES + 31) / 32, 256>>>(W2);
    att2_kernel<<<(N_NODES + 255) / 256, 256>>>(asr2, adt2);
    edge2_kernel<<<(E + 255) / 256, 256>>>(E);
    fin2_kernel<<<(N_NODES + 7) / 8, 256>>>(b2, out);
}

// round 7
// speedup vs baseline: 1.6689x; 1.5234x over previous
#include <cuda_runtime.h>
#include <cstdint>

#define N_NODES 50000
#define F_IN    512
#define NH1     8
#define C1      8
#define D1      64   // NH1*C1
#define C2      40
#define ECAP    1600000

// ---------------- scratch (device globals; no allocation) ----------------
__device__ __align__(256) float g_h1  [N_NODES * D1];
__device__ __align__(256) float g_as1 [N_NODES * NH1];
__device__ __align__(256) float g_ad1 [N_NODES * NH1];
__device__ __align__(256) float g_den1[N_NODES * NH1];
__device__ __align__(256) float g_acc1[N_NODES * D1];   // reused as relu output
__device__ __align__(256) float g_h2  [N_NODES * C2];
__device__ __align__(256) float g_as2 [N_NODES];
__device__ __align__(256) float g_ad2 [N_NODES];
__device__ __align__(256) float g_den2[N_NODES];
__device__ __align__(256) float g_acc2[N_NODES * C2];
__device__ __align__(256) int   g_src [ECAP];
__device__ __align__(256) int   g_dst [ECAP];
__device__ int g_is64;   // 1 if edge_index buffer is int64, 0 if int32

__device__ __forceinline__ float leaky(float e) { return e >= 0.f ? e : 0.2f * e; }

__device__ __forceinline__ void red_add4(float* p, float a, float b, float c, float d) {
    asm volatile("red.global.add.v4.f32 [%0], {%1,%2,%3,%4};"
                 :: "l"(p), "f"(a), "f"(b), "f"(c), "f"(d) : "memory");
}

__device__ __forceinline__ uint32_t f2tf32(float f) {
    uint32_t r;
    asm("cvt.rna.tf32.f32 %0, %1;" : "=r"(r) : "f"(f));
    return r;
}

__device__ __forceinline__ void mma_tf32(float* c, const uint32_t* a, const uint32_t* b) {
    asm volatile("mma.sync.aligned.m16n8k8.row.col.f32.tf32.tf32.f32 "
                 "{%0,%1,%2,%3}, {%4,%5,%6,%7}, {%8,%9}, {%0,%1,%2,%3};"
                 : "+f"(c[0]), "+f"(c[1]), "+f"(c[2]), "+f"(c[3])
                 : "r"(a[0]), "r"(a[1]), "r"(a[2]), "r"(a[3]),
                   "r"(b[0]), "r"(b[1]));
}

// ---------------- dtype detect (1 thread) ----------------
__global__ void detect_kernel(const unsigned int* __restrict__ ei_raw) {
    if (threadIdx.x == 0 && blockIdx.x == 0) {
        int all_zero = 1;
        for (int i = 0; i < 32; i++)
            if (ei_raw[2 * i + 1] != 0u) { all_zero = 0; break; }
        g_is64 = all_zero;   // int64 little-endian with values<2^31 -> odd words all zero
    }
}

// ---------------- convert edge index to packed int32 ----------------
__global__ void convert_kernel(const void* __restrict__ ei, int E) {
    int e = blockIdx.x * blockDim.x + threadIdx.x;
    if (e >= E || e >= ECAP) return;
    int s, d;
    if (g_is64) {
        const long long* p = (const long long*)ei;
        s = (int)p[e];
        d = (int)p[E + e];
    } else {
        const int* p = (const int*)ei;
        s = p[e];
        d = p[E + e];
    }
    g_src[e] = s;
    g_dst[e] = d;
}

// ---------------- zero the accumulators ----------------
__global__ void zero_kernel() {
    int i = blockIdx.x * blockDim.x + threadIdx.x;
    int stride = gridDim.x * blockDim.x;
    float4 z = make_float4(0.f, 0.f, 0.f, 0.f);
    for (int j = i; j < N_NODES * D1 / 4;  j += stride) ((float4*)g_acc1)[j] = z;
    for (int j = i; j < N_NODES * NH1 / 4; j += stride) ((float4*)g_den1)[j] = z;
    for (int j = i; j < N_NODES * C2 / 4;  j += stride) ((float4*)g_acc2)[j] = z;
    for (int j = i; j < N_NODES / 4;       j += stride) ((float4*)g_den2)[j] = z;
}

// ---------------- GEMM1 (tensor core tf32): h1[N,64] = x[N,512] @ W1[512,64] ----------------
#define GA_STR 36
#define GB_STR 72
__global__ __launch_bounds__(256) void gemm1_tc(const float* __restrict__ x,
                                                const float* __restrict__ W) {
    __shared__ uint32_t As[128 * GA_STR];  // [m][k], tf32 bits
    __shared__ uint32_t Bs[32 * GB_STR];   // [k][n], tf32 bits
    int tid  = threadIdx.x;
    int m0   = blockIdx.x * 128;
    int wid  = tid >> 5, lane = tid & 31;
    int wm   = wid >> 1, wn = wid & 1;
    int g    = lane >> 2, tig = lane & 3;

    float acc[2][4][4];
#pragma unroll
    for (int mt = 0; mt < 2; mt++)
#pragma unroll
        for (int nt = 0; nt < 4; nt++)
#pragma unroll
            for (int j = 0; j < 4; j++) acc[mt][nt][j] = 0.f;

    for (int k0 = 0; k0 < F_IN; k0 += 32) {
#pragma unroll
        for (int l = 0; l < 4; l++) {
            int idx = l * 256 + tid;
            int m  = idx >> 3;
            int kv = (idx & 7) * 4;
            float4 v = make_float4(0.f, 0.f, 0.f, 0.f);
            if (m0 + m < N_NODES)
                v = *(const float4*)(x + (size_t)(m0 + m) * F_IN + k0 + kv);
            As[m * GA_STR + kv + 0] = f2tf32(v.x);
            As[m * GA_STR + kv + 1] = f2tf32(v.y);
            As[m * GA_STR + kv + 2] = f2tf32(v.z);
            As[m * GA_STR + kv + 3] = f2tf32(v.w);
        }
#pragma unroll
        for (int l = 0; l < 2; l++) {
            int idx = l * 256 + tid;
            int r  = idx >> 4;
            int cv = (idx & 15) * 4;
            float4 v = *(const float4*)(W + (size_t)(k0 + r) * D1 + cv);
            Bs[r * GB_STR + cv + 0] = f2tf32(v.x);
            Bs[r * GB_STR + cv + 1] = f2tf32(v.y);
            Bs[r * GB_STR + cv + 2] = f2tf32(v.z);
            Bs[r * GB_STR + cv + 3] = f2tf32(v.w);
        }
        __syncthreads();
#pragma unroll
        for (int kk = 0; kk < 4; kk++) {
            int kb = kk * 8;
            uint32_t a[2][4], b[4][2];
#pragma unroll
            for (int mt = 0; mt < 2; mt++) {
                int r = wm * 32 + mt * 16;
                a[mt][0] = As[(r + g    ) * GA_STR + kb + tig    ];
                a[mt][1] = As[(r + g + 8) * GA_STR + kb + tig    ];
                a[mt][2] = As[(r + g    ) * GA_STR + kb + tig + 4];
                a[mt][3] = As[(r + g + 8) * GA_STR + kb + tig + 4];
            }
#pragma unroll
            for (int nt = 0; nt < 4; nt++) {
                int c = wn * 32 + nt * 8 + g;
                b[nt][0] = Bs[(kb + tig    ) * GB_STR + c];
                b[nt][1] = Bs[(kb + tig + 4) * GB_STR + c];
            }
#pragma unroll
            for (int mt = 0; mt < 2; mt++)
#pragma unroll
                for (int nt = 0; nt < 4; nt++)
                    mma_tf32(acc[mt][nt], a[mt], b[nt]);
        }
        __syncthreads();
    }
#pragma unroll
    for (int mt = 0; mt < 2; mt++)
#pragma unroll
        for (int nt = 0; nt < 4; nt++) {
            int r = m0 + wm * 32 + mt * 16 + g;
            int c = wn * 32 + nt * 8 + tig * 2;
            if (r < N_NODES)
                *(float2*)(g_h1 + (size_t)r * D1 + c) =
                    make_float2(acc[mt][nt][0], acc[mt][nt][1]);
            if (r + 8 < N_NODES)
                *(float2*)(g_h1 + (size_t)(r + 8) * D1 + c) =
                    make_float2(acc[mt][nt][2], acc[mt][nt][3]);
        }
}

// ---------------- per-node attention logits, layer 1 ----------------
__global__ void att1_kernel(const float* __restrict__ att_src,
                            const float* __restrict__ att_dst) {
    int n = blockIdx.x * blockDim.x + threadIdx.x;
    if (n >= N_NODES) return;
    const float4* hr = (const float4*)(g_h1 + (size_t)n * D1);
    float as[NH1], ad[NH1];
#pragma unroll
    for (int h = 0; h < NH1; h++) { as[h] = 0.f; ad[h] = 0.f; }
#pragma unroll
    for (int j = 0; j < 16; j++) {
        float4 v = __ldg(hr + j);
        float4 s = __ldg((const float4*)att_src + j);
        float4 d = __ldg((const float4*)att_dst + j);
        int h = j >> 1;
        as[h] += v.x * s.x + v.y * s.y + v.z * s.z + v.w * s.w;
        ad[h] += v.x * d.x + v.y * d.y + v.z * d.z + v.w * d.w;
    }
    *(float4*)(g_as1 + (size_t)n * NH1)     = make_float4(as[0], as[1], as[2], as[3]);
    *(float4*)(g_as1 + (size_t)n * NH1 + 4) = make_float4(as[4], as[5], as[6], as[7]);
    *(float4*)(g_ad1 + (size_t)n * NH1)     = make_float4(ad[0], ad[1], ad[2], ad[3]);
    *(float4*)(g_ad1 + (size_t)n * NH1 + 4) = make_float4(ad[4], ad[5], ad[6], ad[7]);
}

// ---------------- layer-1 edge pass: 16 threads per edge (coalesced gather+RED) ----------------
__global__ __launch_bounds__(256) void edge1_kernel(int E) {
    int gtid = blockIdx.x * blockDim.x + threadIdx.x;
    int e = gtid >> 4;
    int t = gtid & 15;
    if (e >= E) return;
    int s = __ldg(g_src + e);
    int d = __ldg(g_dst + e);
    if ((unsigned)s >= N_NODES || (unsigned)d >= N_NODES) return;  // safety net
    int h = t >> 1;
    float es = __ldg(g_as1 + (size_t)s * NH1 + h);
    float ed = __ldg(g_ad1 + (size_t)d * NH1 + h);
    float w = __expf(leaky(es + ed));
    if ((t & 1) == 0)
        atomicAdd(g_den1 + (size_t)d * NH1 + h, w);
    float4 v = __ldg((const float4*)(g_h1 + (size_t)s * D1) + t);
    red_add4(g_acc1 + (size_t)d * D1 + t * 4, v.x * w, v.y * w, v.z * w, v.w * w);
}

// ---------------- layer-1 finalize: self-loop + normalize + bias + relu ----------------
__global__ void fin1_kernel(const float* __restrict__ b1) {
    int i = blockIdx.x * blockDim.x + threadIdx.x;
    if (i >= N_NODES * D1) return;
    int n = i >> 6;
    int c = i & 63;
    int h = c >> 3;
    float ws = __expf(leaky(g_as1[n * NH1 + h] + g_ad1[n * NH1 + h]));
    float v = (g_acc1[i] + ws * g_h1[i]) / (g_den1[n * NH1 + h] + ws + 1e-16f) + __ldg(b1 + c);
    g_acc1[i] = fmaxf(v, 0.f);   // in-place: becomes layer-2 input
}

// ---------------- GEMM2: h2[N,40] = relu[N,64] @ W2[64,40] ----------------
__global__ __launch_bounds__(256) void gemm2_kernel(const float* __restrict__ W2) {
    __shared__ float xs[32 * D1];
    __shared__ float ws[D1 * C2];
    int tid = threadIdx.x;
    int n0 = blockIdx.x * 32;
    for (int j = tid; j < D1 * C2 / 4; j += 256)
        ((float4*)ws)[j] = __ldg((const float4*)W2 + j);
    for (int j = tid; j < 32 * D1 / 4; j += 256) {
        int nn = j >> 4;
        float4 v = make_float4(0.f, 0.f, 0.f, 0.f);
        if (n0 + nn < N_NODES)
            v = *((const float4*)(g_acc1 + (size_t)(n0 + nn) * D1) + (j & 15));
        ((float4*)xs)[j] = v;
    }
    __syncthreads();
#pragma unroll
    for (int t = 0; t < 5; t++) {
        int flat = t * 256 + tid;
        int i = flat / C2;
        int c = flat % C2;
        float sum = 0.f;
#pragma unroll
        for (int kk = 0; kk < D1; kk++) sum += xs[i * D1 + kk] * ws[kk * C2 + c];
        int n = n0 + i;
        if (n < N_NODES) g_h2[(size_t)n * C2 + c] = sum;
    }
}

// ---------------- per-node attention logits, layer 2 ----------------
__global__ void att2_kernel(const float* __restrict__ att_src,
                            const float* __restrict__ att_dst) {
    int n = blockIdx.x * blockDim.x + threadIdx.x;
    if (n >= N_NODES) return;
    const float4* hr = (const float4*)(g_h2 + (size_t)n * C2);
    float as = 0.f, ad = 0.f;
#pragma unroll
    for (int j = 0; j < 10; j++) {
        float4 v = __ldg(hr + j);
        float4 s = __ldg((const float4*)att_src + j);
        float4 d = __ldg((const float4*)att_dst + j);
        as += v.x * s.x + v.y * s.y + v.z * s.z + v.w * s.w;
        ad += v.x * d.x + v.y * d.y + v.z * d.z + v.w * d.w;
    }
    g_as2[n] = as;
    g_ad2[n] = ad;
}

// ---------------- layer-2 edge pass: 8 threads per edge ----------------
__global__ __launch_bounds__(256) void edge2_kernel(int E) {
    int gtid = blockIdx.x * blockDim.x + threadIdx.x;
    int e = gtid >> 3;
    int t = gtid & 7;
    if (e >= E) return;
    int s = __ldg(g_src + e);
    int d = __ldg(g_dst + e);
    if ((unsigned)s >= N_NODES || (unsigned)d >= N_NODES) return;  // safety net
    float w = __expf(leaky(__ldg(g_as2 + s) + __ldg(g_ad2 + d)));
    if (t == 2)
        atomicAdd(g_den2 + d, w);
    const float4* hs = (const float4*)(g_h2 + (size_t)s * C2);
    float* ap = g_acc2 + (size_t)d * C2;
    float4 v = __ldg(hs + t);
    red_add4(ap + t * 4, v.x * w, v.y * w, v.z * w, v.w * w);
    if (t < 2) {
        float4 v2 = __ldg(hs + 8 + t);
        red_add4(ap + (8 + t) * 4, v2.x * w, v2.y * w, v2.z * w, v2.w * w);
    }
}

// ---------------- layer-2 finalize + log_softmax (warp per node) ----------------
__global__ void fin2_kernel(const float* __restrict__ b2, float* __restrict__ out) {
    int gtid = blockIdx.x * blockDim.x + threadIdx.x;
    int n = gtid >> 5;
    int lane = threadIdx.x & 31;
    if (n >= N_NODES) return;
    float ws = __expf(leaky(g_as2[n] + g_ad2[n]));
    float inv = 1.f / (g_den2[n] + ws + 1e-16f);
    int c0 = lane, c1 = lane + 32;
    float v0, v1 = -1e30f;
    v0 = (g_acc2[(size_t)n * C2 + c0] + ws * g_h2[(size_t)n * C2 + c0]) * inv + __ldg(b2 + c0);
    if (c1 < C2)
        v1 = (g_acc2[(size_t)n * C2 + c1] + ws * g_h2[(size_t)n * C2 + c1]) * inv + __ldg(b2 + c1);
    float m = fmaxf(v0, v1);
#pragma unroll
    for (int o = 16; o; o >>= 1) m = fmaxf(m, __shfl_xor_sync(0xffffffffu, m, o));
    float sEx = __expf(v0 - m) + ((c1 < C2) ? __expf(v1 - m) : 0.f);
#pragma unroll
    for (int o = 16; o; o >>= 1) sEx += __shfl_xor_sync(0xffffffffu, sEx, o);
    float lse = m + __logf(sEx);
    out[(size_t)n * C2 + c0] = v0 - lse;
    if (c1 < C2) out[(size_t)n * C2 + c1] = v1 - lse;
}

// ---------------- launch ----------------
extern "C" void kernel_launch(void* const* d_in, const int* in_sizes, int n_in,
                              void* d_out, int out_size) {
    const float* x    = (const float*)d_in[0];
    const void*  ei   = d_in[1];
    const float* W1   = (const float*)d_in[2];
    const float* asr1 = (const float*)d_in[3];
    const float* adt1 = (const float*)d_in[4];
    const float* b1   = (const float*)d_in[5];
    const float* W2   = (const float*)d_in[6];
    const float* asr2 = (const float*)d_in[7];
    const float* adt2 = (const float*)d_in[8];
    const float* b2   = (const float*)d_in[9];
    int E = in_sizes[1] / 2;
    float* out = (float*)d_out;

    detect_kernel<<<1, 32>>>((const unsigned int*)ei);
    convert_kernel<<<(E + 255) / 256, 256>>>(ei, E);
    zero_kernel<<<1024, 256>>>();
    gemm1_tc<<<(N_NODES + 127) / 128, 256>>>(x, W1);
    att1_kernel<<<(N_NODES + 255) / 256, 256>>>(asr1, adt1);
    {
        long long tot = 16LL * E;
        edge1_kernel<<<(int)((tot + 255) / 256), 256>>>(E);
    }
    fin1_kernel<<<(N_NODES * D1 + 255) / 256, 256>>>(b1);
    gemm2_kernel<<<(N_NODES + 31) / 32, 256>>>(W2);
    att2_kernel<<<(N_NODES + 255) / 256, 256>>>(asr2, adt2);
    {
        long long tot = 8LL * E;
        edge2_kernel<<<(int)((tot + 255) / 256), 256>>>(E);
    }
    fin2_kernel<<<(N_NODES + 7) / 8, 256>>>(b2, out);
}

// round 8
// speedup vs baseline: 1.9105x; 1.1447x over previous
#include <cuda_runtime.h>
#include <cstdint>

#define N_NODES 50000
#define F_IN    512
#define NH1     8
#define C1      8
#define D1      64   // NH1*C1
#define C2      40
#define ECAP    1600000

// ---------------- scratch (device globals; no allocation) ----------------
__device__ __align__(256) float g_h1  [N_NODES * D1];
__device__ __align__(256) float g_as1 [N_NODES * NH1];
__device__ __align__(256) float g_ad1 [N_NODES * NH1];
__device__ __align__(256) float g_acc1[N_NODES * D1];   // layer-1 output (relu)
__device__ __align__(256) float g_h2  [N_NODES * C2];
__device__ __align__(256) float g_as2 [N_NODES];
__device__ __align__(256) float g_ad2 [N_NODES];
__device__ __align__(256) int   g_src [ECAP];
__device__ __align__(256) int   g_dst [ECAP];
__device__ __align__(256) int   g_esrc[ECAP];           // src sorted by dst
__device__ __align__(256) int   g_deg [N_NODES];
__device__ __align__(256) int   g_pos [N_NODES];
__device__ __align__(256) int   g_off [N_NODES + 1];
__device__ int g_is64;   // 1 if edge_index buffer is int64, 0 if int32

__device__ __forceinline__ float leaky(float e) { return e >= 0.f ? e : 0.2f * e; }

__device__ __forceinline__ uint32_t f2tf32(float f) {
    uint32_t r;
    asm("cvt.rna.tf32.f32 %0, %1;" : "=r"(r) : "f"(f));
    return r;
}

__device__ __forceinline__ void mma_tf32(float* c, const uint32_t* a, const uint32_t* b) {
    asm volatile("mma.sync.aligned.m16n8k8.row.col.f32.tf32.tf32.f32 "
                 "{%0,%1,%2,%3}, {%4,%5,%6,%7}, {%8,%9}, {%0,%1,%2,%3};"
                 : "+f"(c[0]), "+f"(c[1]), "+f"(c[2]), "+f"(c[3])
                 : "r"(a[0]), "r"(a[1]), "r"(a[2]), "r"(a[3]),
                   "r"(b[0]), "r"(b[1]));
}

// ---------------- dtype detect (1 thread) ----------------
__global__ void detect_kernel(const unsigned int* __restrict__ ei_raw) {
    if (threadIdx.x == 0 && blockIdx.x == 0) {
        int all_zero = 1;
        for (int i = 0; i < 32; i++)
            if (ei_raw[2 * i + 1] != 0u) { all_zero = 0; break; }
        g_is64 = all_zero;   // int64 little-endian with values<2^31 -> odd words all zero
    }
}

// ---------------- zero deg/pos counters ----------------
__global__ void zero_kernel() {
    int i = blockIdx.x * blockDim.x + threadIdx.x;
    if (i < N_NODES) { g_deg[i] = 0; g_pos[i] = 0; }
}

// ---------------- convert edge index to int32 + dst histogram ----------------
__global__ void convert_kernel(const void* __restrict__ ei, int E) {
    int e = blockIdx.x * blockDim.x + threadIdx.x;
    if (e >= E || e >= ECAP) return;
    int s, d;
    if (g_is64) {
        const long long* p = (const long long*)ei;
        s = (int)p[e];
        d = (int)p[E + e];
    } else {
        const int* p = (const int*)ei;
        s = p[e];
        d = p[E + e];
    }
    g_src[e] = s;
    g_dst[e] = d;
    if ((unsigned)s < N_NODES && (unsigned)d < N_NODES)
        atomicAdd(g_deg + d, 1);
}

// ---------------- exclusive scan of degrees (one block, 1024 threads) ----------------
__global__ __launch_bounds__(1024) void scan_kernel() {
    __shared__ int sh[1024];
    int t = threadIdx.x;
    const int CH = (N_NODES + 1023) / 1024;   // 49
    int base = t * CH;
    int sum = 0;
    for (int j = 0; j < CH; j++) {
        int idx = base + j;
        if (idx < N_NODES) sum += g_deg[idx];
    }
    sh[t] = sum;
    __syncthreads();
    for (int off = 1; off < 1024; off <<= 1) {
        int x = 0;
        if (t >= off) x = sh[t - off];
        __syncthreads();
        sh[t] += x;
        __syncthreads();
    }
    int run = sh[t] - sum;   // exclusive prefix for this chunk
    for (int j = 0; j < CH; j++) {
        int idx = base + j;
        if (idx < N_NODES) {
            g_off[idx] = run;
            run += g_deg[idx];
        }
    }
    if (t == 1023) g_off[N_NODES] = sh[1023];
}

// ---------------- scatter edges into CSR buckets ----------------
__global__ void scatter_kernel(int E) {
    int e = blockIdx.x * blockDim.x + threadIdx.x;
    if (e >= E || e >= ECAP) return;
    int s = g_src[e];
    int d = g_dst[e];
    if ((unsigned)s >= N_NODES || (unsigned)d >= N_NODES) return;
    int pos = g_off[d] + atomicAdd(g_pos + d, 1);
    g_esrc[pos] = s;
}

// ---------------- GEMM1 (tensor core tf32): h1[N,64] = x[N,512] @ W1[512,64] ----------------
#define GA_STR 36
#define GB_STR 72
__global__ __launch_bounds__(256) void gemm1_tc(const float* __restrict__ x,
                                                const float* __restrict__ W) {
    __shared__ uint32_t As[128 * GA_STR];  // [m][k], tf32 bits
    __shared__ uint32_t Bs[32 * GB_STR];   // [k][n], tf32 bits
    int tid  = threadIdx.x;
    int m0   = blockIdx.x * 128;
    int wid  = tid >> 5, lane = tid & 31;
    int wm   = wid >> 1, wn = wid & 1;
    int g    = lane >> 2, tig = lane & 3;

    float acc[2][4][4];
#pragma unroll
    for (int mt = 0; mt < 2; mt++)
#pragma unroll
        for (int nt = 0; nt < 4; nt++)
#pragma unroll
            for (int j = 0; j < 4; j++) acc[mt][nt][j] = 0.f;

    for (int k0 = 0; k0 < F_IN; k0 += 32) {
#pragma unroll
        for (int l = 0; l < 4; l++) {
            int idx = l * 256 + tid;
            int m  = idx >> 3;
            int kv = (idx & 7) * 4;
            float4 v = make_float4(0.f, 0.f, 0.f, 0.f);
            if (m0 + m < N_NODES)
                v = *(const float4*)(x + (size_t)(m0 + m) * F_IN + k0 + kv);
            As[m * GA_STR + kv + 0] = f2tf32(v.x);
            As[m * GA_STR + kv + 1] = f2tf32(v.y);
            As[m * GA_STR + kv + 2] = f2tf32(v.z);
            As[m * GA_STR + kv + 3] = f2tf32(v.w);
        }
#pragma unroll
        for (int l = 0; l < 2; l++) {
            int idx = l * 256 + tid;
            int r  = idx >> 4;
            int cv = (idx & 15) * 4;
            float4 v = *(const float4*)(W + (size_t)(k0 + r) * D1 + cv);
            Bs[r * GB_STR + cv + 0] = f2tf32(v.x);
            Bs[r * GB_STR + cv + 1] = f2tf32(v.y);
            Bs[r * GB_STR + cv + 2] = f2tf32(v.z);
            Bs[r * GB_STR + cv + 3] = f2tf32(v.w);
        }
        __syncthreads();
#pragma unroll
        for (int kk = 0; kk < 4; kk++) {
            int kb = kk * 8;
            uint32_t a[2][4], b[4][2];
#pragma unroll
            for (int mt = 0; mt < 2; mt++) {
                int r = wm * 32 + mt * 16;
                a[mt][0] = As[(r + g    ) * GA_STR + kb + tig    ];
                a[mt][1] = As[(r + g + 8) * GA_STR + kb + tig    ];
                a[mt][2] = As[(r + g    ) * GA_STR + kb + tig + 4];
                a[mt][3] = As[(r + g + 8) * GA_STR + kb + tig + 4];
            }
#pragma unroll
            for (int nt = 0; nt < 4; nt++) {
                int c = wn * 32 + nt * 8 + g;
                b[nt][0] = Bs[(kb + tig    ) * GB_STR + c];
                b[nt][1] = Bs[(kb + tig + 4) * GB_STR + c];
            }
#pragma unroll
            for (int mt = 0; mt < 2; mt++)
#pragma unroll
                for (int nt = 0; nt < 4; nt++)
                    mma_tf32(acc[mt][nt], a[mt], b[nt]);
        }
        __syncthreads();
    }
#pragma unroll
    for (int mt = 0; mt < 2; mt++)
#pragma unroll
        for (int nt = 0; nt < 4; nt++) {
            int r = m0 + wm * 32 + mt * 16 + g;
            int c = wn * 32 + nt * 8 + tig * 2;
            if (r < N_NODES)
                *(float2*)(g_h1 + (size_t)r * D1 + c) =
                    make_float2(acc[mt][nt][0], acc[mt][nt][1]);
            if (r + 8 < N_NODES)
                *(float2*)(g_h1 + (size_t)(r + 8) * D1 + c) =
                    make_float2(acc[mt][nt][2], acc[mt][nt][3]);
        }
}

// ---------------- per-node attention logits, layer 1 ----------------
__global__ void att1_kernel(const float* __restrict__ att_src,
                            const float* __restrict__ att_dst) {
    int n = blockIdx.x * blockDim.x + threadIdx.x;
    if (n >= N_NODES) return;
    const float4* hr = (const float4*)(g_h1 + (size_t)n * D1);
    float as[NH1], ad[NH1];
#pragma unroll
    for (int h = 0; h < NH1; h++) { as[h] = 0.f; ad[h] = 0.f; }
#pragma unroll
    for (int j = 0; j < 16; j++) {
        float4 v = __ldg(hr + j);
        float4 s = __ldg((const float4*)att_src + j);
        float4 d = __ldg((const float4*)att_dst + j);
        int h = j >> 1;
        as[h] += v.x * s.x + v.y * s.y + v.z * s.z + v.w * s.w;
        ad[h] += v.x * d.x + v.y * d.y + v.z * d.z + v.w * d.w;
    }
    *(float4*)(g_as1 + (size_t)n * NH1)     = make_float4(as[0], as[1], as[2], as[3]);
    *(float4*)(g_as1 + (size_t)n * NH1 + 4) = make_float4(as[4], as[5], as[6], as[7]);
    *(float4*)(g_ad1 + (size_t)n * NH1)     = make_float4(ad[0], ad[1], ad[2], ad[3]);
    *(float4*)(g_ad1 + (size_t)n * NH1 + 4) = make_float4(ad[4], ad[5], ad[6], ad[7]);
}

// ---------------- layer-1 aggregation (CSR, fused normalize+bias+relu) ----------------
// 16 threads per dst node; thread t owns channels 4t..4t+3 (head = t>>1).
__global__ __launch_bounds__(256) void agg1_kernel(const float* __restrict__ b1) {
    int gtid = blockIdx.x * blockDim.x + threadIdx.x;
    int n = gtid >> 4;
    int t = gtid & 15;
    if (n >= N_NODES) return;
    int h = t >> 1;
    int i0 = __ldg(g_off + n), i1 = __ldg(g_off + n + 1);
    float adn = __ldg(g_ad1 + (size_t)n * NH1 + h);
    float4 acc = make_float4(0.f, 0.f, 0.f, 0.f);
    float dsum = 0.f;
    for (int i = i0; i < i1; i++) {
        int s = __ldg(g_esrc + i);
        float w = __expf(leaky(__ldg(g_as1 + (size_t)s * NH1 + h) + adn));
        float4 v = __ldg((const float4*)(g_h1 + (size_t)s * D1) + t);
        acc.x += w * v.x; acc.y += w * v.y; acc.z += w * v.z; acc.w += w * v.w;
        dsum += w;
    }
    // self-loop
    {
        float ws = __expf(leaky(__ldg(g_as1 + (size_t)n * NH1 + h) + adn));
        float4 v = __ldg((const float4*)(g_h1 + (size_t)n * D1) + t);
        acc.x += ws * v.x; acc.y += ws * v.y; acc.z += ws * v.z; acc.w += ws * v.w;
        dsum += ws;
    }
    float inv = 1.f / (dsum + 1e-16f);
    float4 bb = __ldg((const float4*)b1 + t);
    float4 o;
    o.x = fmaxf(acc.x * inv + bb.x, 0.f);
    o.y = fmaxf(acc.y * inv + bb.y, 0.f);
    o.z = fmaxf(acc.z * inv + bb.z, 0.f);
    o.w = fmaxf(acc.w * inv + bb.w, 0.f);
    *((float4*)(g_acc1 + (size_t)n * D1) + t) = o;
}

// ---------------- GEMM2: h2[N,40] = relu[N,64] @ W2[64,40] ----------------
__global__ __launch_bounds__(256) void gemm2_kernel(const float* __restrict__ W2) {
    __shared__ float xs[32 * D1];
    __shared__ float ws[D1 * C2];
    int tid = threadIdx.x;
    int n0 = blockIdx.x * 32;
    for (int j = tid; j < D1 * C2 / 4; j += 256)
        ((float4*)ws)[j] = __ldg((const float4*)W2 + j);
    for (int j = tid; j < 32 * D1 / 4; j += 256) {
        int nn = j >> 4;
        float4 v = make_float4(0.f, 0.f, 0.f, 0.f);
        if (n0 + nn < N_NODES)
            v = *((const float4*)(g_acc1 + (size_t)(n0 + nn) * D1) + (j & 15));
        ((float4*)xs)[j] = v;
    }
    __syncthreads();
#pragma unroll
    for (int t = 0; t < 5; t++) {
        int flat = t * 256 + tid;
        int i = flat / C2;
        int c = flat % C2;
        float sum = 0.f;
#pragma unroll
        for (int kk = 0; kk < D1; kk++) sum += xs[i * D1 + kk] * ws[kk * C2 + c];
        int n = n0 + i;
        if (n < N_NODES) g_h2[(size_t)n * C2 + c] = sum;
    }
}

// ---------------- per-node attention logits, layer 2 ----------------
__global__ void att2_kernel(const float* __restrict__ att_src,
                            const float* __restrict__ att_dst) {
    int n = blockIdx.x * blockDim.x + threadIdx.x;
    if (n >= N_NODES) return;
    const float4* hr = (const float4*)(g_h2 + (size_t)n * C2);
    float as = 0.f, ad = 0.f;
#pragma unroll
    for (int j = 0; j < 10; j++) {
        float4 v = __ldg(hr + j);
        float4 s = __ldg((const float4*)att_src + j);
        float4 d = __ldg((const float4*)att_dst + j);
        as += v.x * s.x + v.y * s.y + v.z * s.z + v.w * s.w;
        ad += v.x * d.x + v.y * d.y + v.z * d.z + v.w * d.w;
    }
    g_as2[n] = as;
    g_ad2[n] = ad;
}

// ---------------- layer-2 aggregation (CSR, fused log_softmax) ----------------
// One warp per dst node; lane owns channel lane (and 32+lane for lane<8).
__global__ __launch_bounds__(256) void agg2_kernel(const float* __restrict__ b2,
                                                   float* __restrict__ out) {
    int gtid = blockIdx.x * blockDim.x + threadIdx.x;
    int n = gtid >> 5;
    int lane = threadIdx.x & 31;
    if (n >= N_NODES) return;
    int i0 = __ldg(g_off + n), i1 = __ldg(g_off + n + 1);
    float adn = __ldg(g_ad2 + n);
    float acc0 = 0.f, acc1 = 0.f, dsum = 0.f;
    for (int i = i0; i < i1; i++) {
        int s = __ldg(g_esrc + i);
        float w = __expf(leaky(__ldg(g_as2 + s) + adn));
        const float* hs = g_h2 + (size_t)s * C2;
        acc0 += w * __ldg(hs + lane);
        if (lane < 8) acc1 += w * __ldg(hs + 32 + lane);
        dsum += w;
    }
    // self-loop
    {
        float ws = __expf(leaky(__ldg(g_as2 + n) + adn));
        const float* hn = g_h2 + (size_t)n * C2;
        acc0 += ws * __ldg(hn + lane);
        if (lane < 8) acc1 += ws * __ldg(hn + 32 + lane);
        dsum += ws;
    }
    float inv = 1.f / (dsum + 1e-16f);
    float v0 = acc0 * inv + __ldg(b2 + lane);
    float v1 = -1e30f;
    if (lane < 8) v1 = acc1 * inv + __ldg(b2 + 32 + lane);
    float m = fmaxf(v0, v1);
#pragma unroll
    for (int o = 16; o; o >>= 1) m = fmaxf(m, __shfl_xor_sync(0xffffffffu, m, o));
    float sEx = __expf(v0 - m) + ((lane < 8) ? __expf(v1 - m) : 0.f);
#pragma unroll
    for (int o = 16; o; o >>= 1) sEx += __shfl_xor_sync(0xffffffffu, sEx, o);
    float lse = m + __logf(sEx);
    out[(size_t)n * C2 + lane] = v0 - lse;
    if (lane < 8) out[(size_t)n * C2 + 32 + lane] = v1 - lse;
}

// ---------------- launch ----------------
extern "C" void kernel_launch(void* const* d_in, const int* in_sizes, int n_in,
                              void* d_out, int out_size) {
    const float* x    = (const float*)d_in[0];
    const void*  ei   = d_in[1];
    const float* W1   = (const float*)d_in[2];
    const float* asr1 = (const float*)d_in[3];
    const float* adt1 = (const float*)d_in[4];
    const float* b1   = (const float*)d_in[5];
    const float* W2   = (const float*)d_in[6];
    const float* asr2 = (const float*)d_in[7];
    const float* adt2 = (const float*)d_in[8];
    const float* b2   = (const float*)d_in[9];
    int E = in_sizes[1] / 2;
    float* out = (float*)d_out;

    detect_kernel<<<1, 32>>>((const unsigned int*)ei);
    zero_kernel<<<(N_NODES + 255) / 256, 256>>>();
    convert_kernel<<<(E + 255) / 256, 256>>>(ei, E);
    scan_kernel<<<1, 1024>>>();
    scatter_kernel<<<(E + 255) / 256, 256>>>(E);
    gemm1_tc<<<(N_NODES + 127) / 128, 256>>>(x, W1);
    att1_kernel<<<(N_NODES + 255) / 256, 256>>>(asr1, adt1);
    agg1_kernel<<<(N_NODES * 16 + 255) / 256, 256>>>(b1);
    gemm2_kernel<<<(N_NODES + 31) / 32, 256>>>(W2);
    att2_kernel<<<(N_NODES + 255) / 256, 256>>>(asr2, adt2);
    agg2_kernel<<<(N_NODES * 32 + 255) / 256, 256>>>(b2, out);
}

// round 9
// speedup vs baseline: 2.3958x; 1.2540x over previous
#include <cuda_runtime.h>
#include <cstdint>

#define N_NODES 50000
#define F_IN    512
#define NH1     8
#define C1      8
#define D1      64   // NH1*C1
#define C2      40
#define ECAP    1600000
#define SCAN_NB ((N_NODES + 255) / 256)   // 196

// ---------------- scratch (device globals; no allocation) ----------------
__device__ __align__(256) float g_h1  [N_NODES * D1];
__device__ __align__(256) float g_as1 [N_NODES * NH1];
__device__ __align__(256) float g_ad1 [N_NODES * NH1];
__device__ __align__(256) float g_acc1[N_NODES * D1];   // layer-1 output (relu)
__device__ __align__(256) float g_h2  [N_NODES * C2];
__device__ __align__(256) float g_as2 [N_NODES];
__device__ __align__(256) float g_ad2 [N_NODES];
__device__ __align__(256) int   g_src [ECAP];
__device__ __align__(256) int   g_dst [ECAP];
__device__ __align__(256) int   g_esrc[ECAP];           // src sorted by dst
__device__ __align__(256) int   g_deg [N_NODES];
__device__ __align__(256) int   g_pos [N_NODES];
__device__ __align__(256) int   g_off [N_NODES + 1];
__device__ __align__(256) int   g_bsum[SCAN_NB + 1];
__device__ __align__(256) int   g_boff[SCAN_NB + 1];
__device__ int g_is64;   // 1 if edge_index buffer is int64, 0 if int32

__device__ __forceinline__ float leaky(float e) { return e >= 0.f ? e : 0.2f * e; }

__device__ __forceinline__ void mma_tf32(float* c, const uint32_t* a, const uint32_t* b) {
    asm volatile("mma.sync.aligned.m16n8k8.row.col.f32.tf32.tf32.f32 "
                 "{%0,%1,%2,%3}, {%4,%5,%6,%7}, {%8,%9}, {%0,%1,%2,%3};"
                 : "+f"(c[0]), "+f"(c[1]), "+f"(c[2]), "+f"(c[3])
                 : "r"(a[0]), "r"(a[1]), "r"(a[2]), "r"(a[3]),
                   "r"(b[0]), "r"(b[1]));
}

__device__ __forceinline__ void cp16(uint32_t* dst_smem, const void* src, bool valid) {
    uint32_t d = (uint32_t)__cvta_generic_to_shared(dst_smem);
    int sz = valid ? 16 : 0;
    asm volatile("cp.async.cg.shared.global [%0], [%1], 16, %2;"
                 :: "r"(d), "l"(src), "r"(sz));
}

// ---------------- dtype detect (1 thread) ----------------
__global__ void detect_kernel(const unsigned int* __restrict__ ei_raw) {
    if (threadIdx.x == 0 && blockIdx.x == 0) {
        int all_zero = 1;
        for (int i = 0; i < 32; i++)
            if (ei_raw[2 * i + 1] != 0u) { all_zero = 0; break; }
        g_is64 = all_zero;   // int64 little-endian with values<2^31 -> odd words all zero
    }
}

// ---------------- zero deg/pos counters ----------------
__global__ void zero_kernel() {
    int i = blockIdx.x * blockDim.x + threadIdx.x;
    if (i < N_NODES) { g_deg[i] = 0; g_pos[i] = 0; }
}

// ---------------- convert edge index to int32 + dst histogram ----------------
__global__ void convert_kernel(const void* __restrict__ ei, int E) {
    int e = blockIdx.x * blockDim.x + threadIdx.x;
    if (e >= E || e >= ECAP) return;
    int s, d;
    if (g_is64) {
        const long long* p = (const long long*)ei;
        s = (int)p[e];
        d = (int)p[E + e];
    } else {
        const int* p = (const int*)ei;
        s = p[e];
        d = p[E + e];
    }
    g_src[e] = s;
    g_dst[e] = d;
    if ((unsigned)s < N_NODES && (unsigned)d < N_NODES)
        atomicAdd(g_deg + d, 1);
}

// ---------------- scan phase 1: per-block exclusive scan of 256 degrees ----------------
__global__ __launch_bounds__(256) void scan1_kernel() {
    __shared__ int sh[256];
    int t = threadIdx.x;
    int i = blockIdx.x * 256 + t;
    int v = (i < N_NODES) ? g_deg[i] : 0;
    sh[t] = v;
    __syncthreads();
#pragma unroll
    for (int off = 1; off < 256; off <<= 1) {
        int x = (t >= off) ? sh[t - off] : 0;
        __syncthreads();
        sh[t] += x;
        __syncthreads();
    }
    if (i < N_NODES) g_off[i] = sh[t] - v;   // exclusive within block
    if (t == 255) g_bsum[blockIdx.x] = sh[255];
}

// ---------------- scan phase 2: scan the 196 block sums (one block) ----------------
__global__ __launch_bounds__(256) void scan2_kernel() {
    __shared__ int sh[256];
    int t = threadIdx.x;
    int v = (t < SCAN_NB) ? g_bsum[t] : 0;
    sh[t] = v;
    __syncthreads();
#pragma unroll
    for (int off = 1; off < 256; off <<= 1) {
        int x = (t >= off) ? sh[t - off] : 0;
        __syncthreads();
        sh[t] += x;
        __syncthreads();
    }
    if (t < SCAN_NB) g_boff[t] = sh[t] - v;
    if (t == 255) g_boff[SCAN_NB] = sh[255];   // grand total
}

// ---------------- scan phase 3: add block offsets ----------------
__global__ void scan3_kernel() {
    int i = blockIdx.x * blockDim.x + threadIdx.x;
    if (i < N_NODES) g_off[i] += g_boff[i >> 8];
    if (i == 0) g_off[N_NODES] = g_boff[SCAN_NB];
}

// ---------------- scatter edges into CSR buckets ----------------
__global__ void scatter_kernel(int E) {
    int e = blockIdx.x * blockDim.x + threadIdx.x;
    if (e >= E || e >= ECAP) return;
    int s = g_src[e];
    int d = g_dst[e];
    if ((unsigned)s >= N_NODES || (unsigned)d >= N_NODES) return;
    int pos = g_off[d] + atomicAdd(g_pos + d, 1);
    g_esrc[pos] = s;
}

// ---------------- GEMM1 (tf32 TC, cp.async double-buffered) ----------------
// h1[N,64] = x[N,512] @ W1[512,64].  Raw fp32 bits fed to tf32 MMA (truncation).
#define GA_STR 36
#define GB_STR 72
#define A_SZ   (128 * GA_STR)
#define B_SZ   (32 * GB_STR)
#define STG    (A_SZ + B_SZ)
#define GEMM1_SMEM (2 * STG * 4)

__global__ __launch_bounds__(256) void gemm1_tc(const float* __restrict__ x,
                                                const float* __restrict__ W) {
    extern __shared__ uint32_t smem[];
    int tid  = threadIdx.x;
    int m0   = blockIdx.x * 128;
    int wid  = tid >> 5, lane = tid & 31;
    int wm   = wid >> 1, wn = wid & 1;
    int g    = lane >> 2, tig = lane & 3;

    float acc[2][4][4];
#pragma unroll
    for (int mt = 0; mt < 2; mt++)
#pragma unroll
        for (int nt = 0; nt < 4; nt++)
#pragma unroll
            for (int j = 0; j < 4; j++) acc[mt][nt][j] = 0.f;

    auto load_tile = [&](int stage, int k0) {
        uint32_t* As = smem + stage * STG;
        uint32_t* Bs = As + A_SZ;
        // A: 128 rows x 32 k = 1024 16B chunks, 4 per thread
#pragma unroll
        for (int l = 0; l < 4; l++) {
            int idx = l * 256 + tid;
            int m  = idx >> 3;
            int kc = idx & 7;
            bool ok = (m0 + m) < N_NODES;
            const float* src = x + (size_t)(ok ? (m0 + m) : 0) * F_IN + k0 + kc * 4;
            cp16(As + m * GA_STR + kc * 4, src, ok);
        }
        // B: 32 rows x 64 cols = 512 chunks, 2 per thread
#pragma unroll
        for (int l = 0; l < 2; l++) {
            int idx = l * 256 + tid;
            int r  = idx >> 4;
            int cc = idx & 15;
            cp16(Bs + r * GB_STR + cc * 4, W + (size_t)(k0 + r) * D1 + cc * 4, true);
        }
        asm volatile("cp.async.commit_group;" ::: "memory");
    };

    load_tile(0, 0);

    const int NIT = F_IN / 32;   // 16
    for (int it = 0; it < NIT; it++) {
        if (it + 1 < NIT) {
            load_tile((it + 1) & 1, (it + 1) * 32);
            asm volatile("cp.async.wait_group 1;" ::: "memory");
        } else {
            asm volatile("cp.async.wait_group 0;" ::: "memory");
        }
        __syncthreads();
        const uint32_t* As = smem + (it & 1) * STG;
        const uint32_t* Bs = As + A_SZ;
#pragma unroll
        for (int kk = 0; kk < 4; kk++) {
            int kb = kk * 8;
            uint32_t a[2][4], b[4][2];
#pragma unroll
            for (int mt = 0; mt < 2; mt++) {
                int r = wm * 32 + mt * 16;
                a[mt][0] = As[(r + g    ) * GA_STR + kb + tig    ];
                a[mt][1] = As[(r + g + 8) * GA_STR + kb + tig    ];
                a[mt][2] = As[(r + g    ) * GA_STR + kb + tig + 4];
                a[mt][3] = As[(r + g + 8) * GA_STR + kb + tig + 4];
            }
#pragma unroll
            for (int nt = 0; nt < 4; nt++) {
                int c = wn * 32 + nt * 8 + g;
                b[nt][0] = Bs[(kb + tig    ) * GB_STR + c];
                b[nt][1] = Bs[(kb + tig + 4) * GB_STR + c];
            }
#pragma unroll
            for (int mt = 0; mt < 2; mt++)
#pragma unroll
                for (int nt = 0; nt < 4; nt++)
                    mma_tf32(acc[mt][nt], a[mt], b[nt]);
        }
        __syncthreads();
    }
#pragma unroll
    for (int mt = 0; mt < 2; mt++)
#pragma unroll
        for (int nt = 0; nt < 4; nt++) {
            int r = m0 + wm * 32 + mt * 16 + g;
            int c = wn * 32 + nt * 8 + tig * 2;
            if (r < N_NODES)
                *(float2*)(g_h1 + (size_t)r * D1 + c) =
                    make_float2(acc[mt][nt][0], acc[mt][nt][1]);
            if (r + 8 < N_NODES)
                *(float2*)(g_h1 + (size_t)(r + 8) * D1 + c) =
                    make_float2(acc[mt][nt][2], acc[mt][nt][3]);
        }
}

// ---------------- per-node attention logits, layer 1 ----------------
__global__ void att1_kernel(const float* __restrict__ att_src,
                            const float* __restrict__ att_dst) {
    int n = blockIdx.x * blockDim.x + threadIdx.x;
    if (n >= N_NODES) return;
    const float4* hr = (const float4*)(g_h1 + (size_t)n * D1);
    float as[NH1], ad[NH1];
#pragma unroll
    for (int h = 0; h < NH1; h++) { as[h] = 0.f; ad[h] = 0.f; }
#pragma unroll
    for (int j = 0; j < 16; j++) {
        float4 v = __ldg(hr + j);
        float4 s = __ldg((const float4*)att_src + j);
        float4 d = __ldg((const float4*)att_dst + j);
        int h = j >> 1;
        as[h] += v.x * s.x + v.y * s.y + v.z * s.z + v.w * s.w;
        ad[h] += v.x * d.x + v.y * d.y + v.z * d.z + v.w * d.w;
    }
    *(float4*)(g_as1 + (size_t)n * NH1)     = make_float4(as[0], as[1], as[2], as[3]);
    *(float4*)(g_as1 + (size_t)n * NH1 + 4) = make_float4(as[4], as[5], as[6], as[7]);
    *(float4*)(g_ad1 + (size_t)n * NH1)     = make_float4(ad[0], ad[1], ad[2], ad[3]);
    *(float4*)(g_ad1 + (size_t)n * NH1 + 4) = make_float4(ad[4], ad[5], ad[6], ad[7]);
}

// ---------------- layer-1 aggregation (CSR, fused normalize+bias+relu) ----------------
// 16 threads per dst node; thread t owns channels 4t..4t+3 (head = t>>1).
__global__ __launch_bounds__(256) void agg1_kernel(const float* __restrict__ b1) {
    int gtid = blockIdx.x * blockDim.x + threadIdx.x;
    int n = gtid >> 4;
    int t = gtid & 15;
    if (n >= N_NODES) return;
    int h = t >> 1;
    int i0 = __ldg(g_off + n), i1 = __ldg(g_off + n + 1);
    float adn = __ldg(g_ad1 + (size_t)n * NH1 + h);
    float4 acc = make_float4(0.f, 0.f, 0.f, 0.f);
    float dsum = 0.f;
    for (int i = i0; i < i1; i++) {
        int s = __ldg(g_esrc + i);
        float w = __expf(leaky(__ldg(g_as1 + (size_t)s * NH1 + h) + adn));
        float4 v = __ldg((const float4*)(g_h1 + (size_t)s * D1) + t);
        acc.x += w * v.x; acc.y += w * v.y; acc.z += w * v.z; acc.w += w * v.w;
        dsum += w;
    }
    // self-loop
    {
        float ws = __expf(leaky(__ldg(g_as1 + (size_t)n * NH1 + h) + adn));
        float4 v = __ldg((const float4*)(g_h1 + (size_t)n * D1) + t);
        acc.x += ws * v.x; acc.y += ws * v.y; acc.z += ws * v.z; acc.w += ws * v.w;
        dsum += ws;
    }
    float inv = 1.f / (dsum + 1e-16f);
    float4 bb = __ldg((const float4*)b1 + t);
    float4 o;
    o.x = fmaxf(acc.x * inv + bb.x, 0.f);
    o.y = fmaxf(acc.y * inv + bb.y, 0.f);
    o.z = fmaxf(acc.z * inv + bb.z, 0.f);
    o.w = fmaxf(acc.w * inv + bb.w, 0.f);
    *((float4*)(g_acc1 + (size_t)n * D1) + t) = o;
}

// ---------------- GEMM2: h2[N,40] = relu[N,64] @ W2[64,40] ----------------
__global__ __launch_bounds__(256) void gemm2_kernel(const float* __restrict__ W2) {
    __shared__ float xs[32 * D1];
    __shared__ float ws[D1 * C2];
    int tid = threadIdx.x;
    int n0 = blockIdx.x * 32;
    for (int j = tid; j < D1 * C2 / 4; j += 256)
        ((float4*)ws)[j] = __ldg((const float4*)W2 + j);
    for (int j = tid; j < 32 * D1 / 4; j += 256) {
        int nn = j >> 4;
        float4 v = make_float4(0.f, 0.f, 0.f, 0.f);
        if (n0 + nn < N_NODES)
            v = *((const float4*)(g_acc1 + (size_t)(n0 + nn) * D1) + (j & 15));
        ((float4*)xs)[j] = v;
    }
    __syncthreads();
#pragma unroll
    for (int t = 0; t < 5; t++) {
        int flat = t * 256 + tid;
        int i = flat / C2;
        int c = flat % C2;
        float sum = 0.f;
#pragma unroll
        for (int kk = 0; kk < D1; kk++) sum += xs[i * D1 + kk] * ws[kk * C2 + c];
        int n = n0 + i;
        if (n < N_NODES) g_h2[(size_t)n * C2 + c] = sum;
    }
}

// ---------------- per-node attention logits, layer 2 ----------------
__global__ void att2_kernel(const float* __restrict__ att_src,
                            const float* __restrict__ att_dst) {
    int n = blockIdx.x * blockDim.x + threadIdx.x;
    if (n >= N_NODES) return;
    const float4* hr = (const float4*)(g_h2 + (size_t)n * C2);
    float as = 0.f, ad = 0.f;
#pragma unroll
    for (int j = 0; j < 10; j++) {
        float4 v = __ldg(hr + j);
        float4 s = __ldg((const float4*)att_src + j);
        float4 d = __ldg((const float4*)att_dst + j);
        as += v.x * s.x + v.y * s.y + v.z * s.z + v.w * s.w;
        ad += v.x * d.x + v.y * d.y + v.z * d.z + v.w * d.w;
    }
    g_as2[n] = as;
    g_ad2[n] = ad;
}

// ---------------- layer-2 aggregation (CSR, fused log_softmax) ----------------
__global__ __launch_bounds__(256) void agg2_kernel(const float* __restrict__ b2,
                                                   float* __restrict__ out) {
    int gtid = blockIdx.x * blockDim.x + threadIdx.x;
    int n = gtid >> 5;
    int lane = threadIdx.x & 31;
    if (n >= N_NODES) return;
    int i0 = __ldg(g_off + n), i1 = __ldg(g_off + n + 1);
    float adn = __ldg(g_ad2 + n);
    float acc0 = 0.f, acc1 = 0.f, dsum = 0.f;
    for (int i = i0; i < i1; i++) {
        int s = __ldg(g_esrc + i);
        float w = __expf(leaky(__ldg(g_as2 + s) + adn));
        const float* hs = g_h2 + (size_t)s * C2;
        acc0 += w * __ldg(hs + lane);
        if (lane < 8) acc1 += w * __ldg(hs + 32 + lane);
        dsum += w;
    }
    // self-loop
    {
        float ws = __expf(leaky(__ldg(g_as2 + n) + adn));
        const float* hn = g_h2 + (size_t)n * C2;
        acc0 += ws * __ldg(hn + lane);
        if (lane < 8) acc1 += ws * __ldg(hn + 32 + lane);
        dsum += ws;
    }
    float inv = 1.f / (dsum + 1e-16f);
    float v0 = acc0 * inv + __ldg(b2 + lane);
    float v1 = -1e30f;
    if (lane < 8) v1 = acc1 * inv + __ldg(b2 + 32 + lane);
    float m = fmaxf(v0, v1);
#pragma unroll
    for (int o = 16; o; o >>= 1) m = fmaxf(m, __shfl_xor_sync(0xffffffffu, m, o));
    float sEx = __expf(v0 - m) + ((lane < 8) ? __expf(v1 - m) : 0.f);
#pragma unroll
    for (int o = 16; o; o >>= 1) sEx += __shfl_xor_sync(0xffffffffu, sEx, o);
    float lse = m + __logf(sEx);
    out[(size_t)n * C2 + lane] = v0 - lse;
    if (lane < 8) out[(size_t)n * C2 + 32 + lane] = v1 - lse;
}

// ---------------- launch ----------------
extern "C" void kernel_launch(void* const* d_in, const int* in_sizes, int n_in,
                              void* d_out, int out_size) {
    const float* x    = (const float*)d_in[0];
    const void*  ei   = d_in[1];
    const float* W1   = (const float*)d_in[2];
    const float* asr1 = (const float*)d_in[3];
    const float* adt1 = (const float*)d_in[4];
    const float* b1   = (const float*)d_in[5];
    const float* W2   = (const float*)d_in[6];
    const float* asr2 = (const float*)d_in[7];
    const float* adt2 = (const float*)d_in[8];
    const float* b2   = (const float*)d_in[9];
    int E = in_sizes[1] / 2;
    float* out = (float*)d_out;

    cudaFuncSetAttribute(gemm1_tc, cudaFuncAttributeMaxDynamicSharedMemorySize,
                         GEMM1_SMEM);

    detect_kernel<<<1, 32>>>((const unsigned int*)ei);
    zero_kernel<<<(N_NODES + 255) / 256, 256>>>();
    convert_kernel<<<(E + 255) / 256, 256>>>(ei, E);
    scan1_kernel<<<SCAN_NB, 256>>>();
    scan2_kernel<<<1, 256>>>();
    scan3_kernel<<<(N_NODES + 255) / 256, 256>>>();
    scatter_kernel<<<(E + 255) / 256, 256>>>(E);
    gemm1_tc<<<(N_NODES + 127) / 128, 256, GEMM1_SMEM>>>(x, W1);
    att1_kernel<<<(N_NODES + 255) / 256, 256>>>(asr1, adt1);
    agg1_kernel<<<(N_NODES * 16 + 255) / 256, 256>>>(b1);
    gemm2_kernel<<<(N_NODES + 31) / 32, 256>>>(W2);
    att2_kernel<<<(N_NODES + 255) / 256, 256>>>(asr2, adt2);
    agg2_kernel<<<(N_NODES * 32 + 255) / 256, 256>>>(b2, out);
}